// round 1
// baseline (speedup 1.0000x reference)
#include <cuda_runtime.h>

#define HH   1024
#define NST  64
#define LL   2048
#define LANES 32
#define CHUNK 64   // LL / LANES

// Scratch: per (h,n): [cmr, cmi, ar, ai] and [w32r, w32i, q32, pad]
__device__ float4 g_par[HH * NST * 2];

// Accurate sincos for |x| <= ~50, independent of compiler fast-math flags.
// Cody-Waite 2-term pi/2 reduction + degree-7/8 minimax polys.
__device__ __forceinline__ void my_sincos(float x, float* sp, float* cp) {
    float k = rintf(x * 0.63661977236f);           // x * 2/pi
    float r = fmaf(k, -1.57079637e+0f, x);         // x - k*PIO2_HI
    r = fmaf(k, 4.37113900e-8f, r);                // + k*PIO2_MID
    int q = ((int)k) & 3;
    float r2 = r * r;
    // sin(r) on [-pi/4, pi/4]
    float s0 = fmaf(r2, -1.9515296e-4f, 8.3321609e-3f);
    s0 = fmaf(r2, s0, -1.6666655e-1f);
    float sr = fmaf(r * r2, s0, r);
    // cos(r)
    float c0 = fmaf(r2, 2.4433157e-5f, -1.3887316e-3f);
    c0 = fmaf(r2, c0, 4.1666646e-2f);
    c0 = fmaf(r2, c0, -0.5f);
    float cr = fmaf(r2, c0, 1.0f);
    float ss = (q & 1) ? cr : sr;
    float cc = (q & 1) ? sr : cr;
    if (q == 1 || q == 2) cc = -cc;
    if (q >= 2) ss = -ss;
    *sp = ss; *cp = cc;
}

// Kernel 1: parameter preprocessing. One thread per (h, n).
// Computes Cm (with ZOH discretization and the factor 2 folded in),
// dtA = (ar, ai), W = w^32 = exp(32*dtA), q32 = |W|^2 = exp(64*ar).
__global__ void s4d_prep(const float* __restrict__ A_real,
                         const float* __restrict__ A_imag,
                         const float* __restrict__ B,
                         const float* __restrict__ C,
                         const float* __restrict__ inv_dt) {
    int i = blockIdx.x * blockDim.x + threadIdx.x;
    if (i >= HH * NST) return;
    int h = i / NST;

    float dt  = __expf(inv_dt[h]);
    float Are = -__expf(A_real[i]);
    float Aim = A_imag[i];
    float ar  = Are * dt;
    float ai  = Aim * dt;

    // exp(dtA) - 1
    float ea = __expf(ar);
    float sa, ca; my_sincos(ai, &sa, &ca);
    float er = fmaf(ea, ca, -1.0f);
    float ei = ea * sa;

    // (exp(dtA)-1) / A
    float inv = 1.0f / fmaf(Are, Are, Aim * Aim);
    float fr = (er * Are + ei * Aim) * inv;
    float fi = (ei * Are - er * Aim) * inv;

    // Cm = B * C * f, then fold the global factor 2 (K = 2*Re(...))
    float br  = B[2 * i], bi  = B[2 * i + 1];
    float c0r = C[2 * i], c0i = C[2 * i + 1];
    float bcr = br * c0r - bi * c0i;
    float bci = br * c0i + bi * c0r;
    float cmr = 2.0f * (bcr * fr - bci * fi);
    float cmi = 2.0f * (bcr * fi + bci * fr);

    // W = w^32 = exp(32*dtA)
    float e32 = __expf(32.0f * ar);
    float s32, c32; my_sincos(32.0f * ai, &s32, &c32);
    float w32r = e32 * c32;
    float w32i = e32 * s32;
    float q32  = e32 * e32;   // |W|^2 exactly

    g_par[2 * i]     = make_float4(cmr, cmi, ar, ai);
    g_par[2 * i + 1] = make_float4(w32r, w32i, q32, 0.0f);
}

// Kernel 2: main Vandermonde contraction.
// One warp per h; lane t owns l = t + 32*k, k = 0..63.
// x_k = Re(Cm * w^(t+32k)) satisfies x_k = p*x_{k-1} - q*x_{k-2}
// with p = 2*Re(w^32), q = |w^32|^2.  3 fma-pipe ops per (n, l).
__global__ void __launch_bounds__(LANES) s4d_main(float* __restrict__ out) {
    int h = blockIdx.x;
    int t = threadIdx.x;
    float tf = (float)t;

    float acc[CHUNK];
#pragma unroll
    for (int j = 0; j < CHUNK; j++) acc[j] = 0.0f;

    const float4* par = &g_par[h * NST * 2];

    for (int n = 0; n < NST; n++) {
        float4 p0 = __ldg(&par[2 * n]);
        float4 p1 = __ldg(&par[2 * n + 1]);
        float cmr = p0.x, cmi = p0.y, ar = p0.z, ai = p0.w;
        float w32r = p1.x, w32i = p1.y, q = p1.z;

        // z = Cm * w^t
        float e = __expf(ar * tf);
        float s, c; my_sincos(ai * tf, &s, &c);
        float zr = e * (cmr * c - cmi * s);
        float zi = e * (cmr * s + cmi * c);

        float x2 = zr;                          // Re(Cm w^t)
        float x1 = zr * w32r - zi * w32i;       // Re(Cm w^(t+32))
        float p  = w32r + w32r;

        acc[0] += x2;
        acc[1] += x1;
#pragma unroll
        for (int j = 2; j < CHUNK; j++) {
            float m = q * x2;
            float x = fmaf(p, x1, -m);
            acc[j] += x;
            x2 = x1;
            x1 = x;
        }
    }

    // out[h, l] with l = 32*j + t : coalesced per j.
    float* o = out + h * LL + t;
#pragma unroll
    for (int j = 0; j < CHUNK; j++) o[j * LANES] = acc[j];
}

extern "C" void kernel_launch(void* const* d_in, const int* in_sizes, int n_in,
                              void* d_out, int out_size) {
    const float* A_real = (const float*)d_in[0];
    const float* A_imag = (const float*)d_in[1];
    const float* B      = (const float*)d_in[2];
    const float* C      = (const float*)d_in[3];
    const float* inv_dt = (const float*)d_in[4];
    float* out = (float*)d_out;

    s4d_prep<<<(HH * NST + 255) / 256, 256>>>(A_real, A_imag, B, C, inv_dt);
    s4d_main<<<HH, LANES>>>(out);
}